// round 6
// baseline (speedup 1.0000x reference)
#include <cuda_runtime.h>
#include <cuda_fp16.h>
#include <mma.h>
#include <cstdint>

using namespace nvcuda;

#define B_   1024
#define H_   512
#define E_   256
#define S_   128
#define T_   128
#define V_   128
#define G4   2048
#define JT_  16
#define NCTA 128
#define NSTEP (S_ + T_ - 1)     // 255
#define THREADS 512
#define LDH  520                // smem ld (halves) for resident W / fc_w rows
#define LDW  72                 // smem ld (halves) for streamed h chunks
#define CHUNKB (128 * LDW * 2)  // 18432 bytes per 64-k chunk
#define WBYTES (128 * LDH * 2)  // 133120: resident W tile
#define GS_B   (128 * 132 * 4)  // 67584: gate-staging fp32 [128 b][132 j]
#define HO_B   (128 * 36 * 4)   // 18432: hout fp32
#define SEQ_SMEM (WBYTES + GS_B + HO_B)               // 219136
#define FC_SMEM  (128 * LDH * 2 + 2 * 128 * LDW * 2)  // 169984

// ---------------- device scratch ----------------
__device__ __half g_W2[2][JT_ * 128 * H_];           // reordered whh fp16: [jt][g*32+h][k]
__device__ float  g_embp[2][(long)V_ * G4];          // emb @ wih^T + bih + bhh (exact fp32)
__device__ __half g_fcw16[V_ * H_];
__device__ float  g_biasfc[16 * V_];
__device__ __half g_hf[2][(long)B_ * H_];            // hidden fp16, double buffered (cross-CTA via L2)
__device__ __half g_hseq[(long)B_ * (T_ - 1) * H_];
__device__ float  g_logits[(long)B_ * (T_ - 1) * V_];
__device__ unsigned g_flag[8][JT_ * 32];             // per (b-group, jt) step counters, 128B apart

__device__ __forceinline__ float sigm(float x) { return 1.f / (1.f + __expf(-x)); }

__device__ __forceinline__ void cpa16(void* dst, const void* src) {
    unsigned d = (unsigned)__cvta_generic_to_shared(dst);
    asm volatile("cp.async.cg.shared.global [%0], [%1], 16;\n" :: "r"(d), "l"(src));
}
#define CPC()  asm volatile("cp.async.commit_group;\n" ::: "memory")
#define CPW(n) asm volatile("cp.async.wait_group %0;\n" :: "n"(n) : "memory")

__device__ __forceinline__ unsigned ldacq(const unsigned* p) {
    unsigned v;
    asm volatile("ld.acquire.gpu.global.u32 %0, [%1];" : "=r"(v) : "l"(p));
    return v;
}
__device__ __forceinline__ void strel(unsigned* p, unsigned v) {
    asm volatile("st.release.gpu.global.u32 [%0], %1;" :: "l"(p), "r"(v));
}

// wait until the 4 producers of chunk-pair p = {chunks p, p+4} have published step >= st
// producers: jt = {2p, 2p+1, 2p+8, 2p+9}; one lane spins per flag (lanes repeat mod 4)
__device__ __forceinline__ void wait_pair(const unsigned* fbase, int p, unsigned st) {
    const int lane = threadIdx.x & 31;
    const int idx  = ((lane & 2) ? 8 : 0) + 2 * p + (lane & 1);
    const unsigned* f = fbase + idx * 32;
    while (ldacq(f) < st) __nanosleep(32);
    __syncwarp();
}

// copy 64-k chunk ch of this CTA's h tile into smem buffer (all 512 threads)
#define CPCHUNK(buf, ch)                                                          \
    for (int i_ = threadIdx.x; i_ < 128 * 8; i_ += THREADS) {                     \
        int r_ = i_ >> 3, q_ = i_ & 7;                                            \
        cpa16((buf) + r_ * LDW + q_ * 8, hg + (long)(b0 + r_) * H_ + (ch) * 64 + q_ * 8); \
    }

// ---------------- prep A: embproj = emb @ wih^T + bih + bhh (exact fp32) ----------------
__global__ void prep_embproj(const float* __restrict__ emb, const float* __restrict__ wih,
                             const float* __restrict__ bih, const float* __restrict__ bhh,
                             int is_dec)
{
    __shared__ float er[E_];
    int v = blockIdx.x;
    int n = blockIdx.y * 256 + threadIdx.x;
    er[threadIdx.x] = emb[(long)v * E_ + threadIdx.x];
    __syncthreads();
    float s = bih[n] + bhh[n];
    const float* wr = wih + (long)n * E_;
    #pragma unroll 8
    for (int k = 0; k < E_; k++) s += er[k] * wr[k];
    g_embp[is_dec][(long)v * G4 + n] = s;
}

// ---------------- prep B: reorder whh fp16, fc weights, bias tile, zero h0, reset flags --
__global__ void prep2(const float* __restrict__ enc_whh, const float* __restrict__ dec_whh,
                      const float* __restrict__ fc_w,    const float* __restrict__ fc_b)
{
    if (blockIdx.x == 0 && threadIdx.x < 8 * JT_ * 32)
        ((unsigned*)g_flag)[threadIdx.x % (8 * JT_ * 32)] = 0u;
    const long NW  = (long)JT_ * 128 * H_;
    const long NFC = (long)V_ * H_;
    const long NB  = 16L * V_;
    const long NS  = (long)B_ * H_;
    const long total = 2 * NW + NFC + NB + NS;
    for (long i = (long)blockIdx.x * blockDim.x + threadIdx.x; i < total;
         i += (long)gridDim.x * blockDim.x) {
        long r = i;
        if (r < 2 * NW) {
            int ed = (int)(r / NW);
            long l = r % NW;
            int jt = (int)(l / (128L * H_));
            int rr = (int)((l / H_) % 128);
            int k  = (int)(l % H_);
            int g = rr >> 5, hh = rr & 31;
            long n = (long)g * H_ + jt * 32 + hh;
            const float* whh = ed ? dec_whh : enc_whh;
            g_W2[ed][l] = __float2half(whh[n * H_ + k]);
        } else if (r < 2 * NW + NFC) {
            long l = r - 2 * NW;
            g_fcw16[l] = __float2half(fc_w[l]);
        } else if (r < 2 * NW + NFC + NB) {
            long l = r - 2 * NW - NFC;
            g_biasfc[l] = fc_b[l % V_];
        } else {
            long l = r - 2 * NW - NFC - NB;
            g_hf[0][l] = __float2half(0.f);
        }
    }
}

// ---------------- persistent kernel: all 255 LSTM steps ----------------
// CTA (bt, jt): batch rows bt*128..+127, h-dims jt*32..+31 (x4 gates = 128 gate rows).
// 16 warps: wk = warp>>3 splits K; (wj, wbt) tile 16j x 32b x 2cb. c state in wk=0 regs.
// Cross-CTA h exchange: STG -> syncthreads -> tid0 fence+release flag; consumers gate each
// chunk-pair cp.async on the 4 producer flags (acquire). Fully pipelined across CTAs.
__global__ __launch_bounds__(THREADS, 1) void seq_kernel(
    const int* __restrict__ src, const int* __restrict__ tgt)
{
    extern __shared__ __align__(16) char smem[];
    __half* Ws = (__half*)smem;                       // [128 gate-row][LDH k] resident
    __half* hb[4];
    #pragma unroll
    for (int i = 0; i < 4; i++) hb[i] = (__half*)(smem + WBYTES + i * CHUNKB);
    float* GS   = (float*)(smem + WBYTES);            // [128 b][132 j] gate staging (aliases hb)
    float* hout = (float*)(smem + WBYTES + GS_B);     // [128 b][36 h]
    __shared__ int tok_s[128];

    const int tid  = threadIdx.x;
    const int warp = tid >> 5;
    const int wk   = warp >> 3;         // K half
    const int wj   = warp & 1;          // j sub-tile (16)
    const int wbt  = (warp >> 1) & 3;   // batch sub-tile (32)
    const int jt   = blockIdx.x & 15;
    const int b0   = (blockIdx.x >> 4) * 128;
    const int btg  = blockIdx.x >> 4;
    const unsigned* fbase = g_flag[btg];
    unsigned* my_flag = &g_flag[btg][jt * 32];

    // resident encoder W tile
    {
        const __half* __restrict__ W = g_W2[0] + (long)jt * 128 * H_;
        for (int i = tid; i < 128 * 64; i += THREADS) {
            int r = i >> 6, q = i & 63;
            cpa16(Ws + r * LDH + q * 8, W + (long)r * H_ + q * 8);
        }
        CPC(); CPW(0);
        __syncthreads();
    }

    // persistent cell state (wk=0 warps only)
    wmma::fragment<wmma::accumulator, 16, 16, 16, float> cfr[2];
    wmma::fill_fragment(cfr[0], 0.f);
    wmma::fill_fragment(cfr[1], 0.f);

    for (int st = 0; st < NSTEP; ++st) {
        const int is_dec = st >= S_;
        const int t   = is_dec ? st - S_ : st;
        const int par = st & 1;
        const int* __restrict__ tok = is_dec ? tgt : src;
        const __half* __restrict__ hg = g_hf[par];

        if (st == S_) {   // swap to decoder weights (CTA-local)
            const __half* __restrict__ W = g_W2[1] + (long)jt * 128 * H_;
            for (int i = tid; i < 128 * 64; i += THREADS) {
                int r = i >> 6, q = i & 63;
                cpa16(Ws + r * LDH + q * 8, W + (long)r * H_ + q * 8);
            }
            CPC(); CPW(0);
            __syncthreads();
        }

        if (tid < 128) tok_s[tid] = tok[(long)(b0 + tid) * 128 + t];

        // prologue: pair0 = chunks {0,4}, pair1 = {1,5} — gated on producer flags
        wait_pair(fbase, 0, (unsigned)st);
        CPCHUNK(hb[0], 0); CPCHUNK(hb[2], 4); CPC();
        wait_pair(fbase, 1, (unsigned)st);
        CPCHUNK(hb[1], 1); CPCHUNK(hb[3], 5); CPC();

        wmma::fragment<wmma::accumulator, 16, 16, 16, float> acc[4][2];
        #pragma unroll
        for (int g = 0; g < 4; g++) {
            wmma::fill_fragment(acc[g][0], 0.f);
            wmma::fill_fragment(acc[g][1], 0.f);
        }

        #pragma unroll 1
        for (int c = 0; c < 4; c++) {
            if (c < 3) { CPW(1); } else { CPW(0); }
            __syncthreads();
            const __half* cw = hb[2 * wk + (c & 1)];
            const int ch = wk * 4 + c;           // this warp's K chunk
            #pragma unroll
            for (int kk = 0; kk < 4; kk++) {
                wmma::fragment<wmma::matrix_b, 16, 16, 16, half, wmma::col_major> bf[2];
                #pragma unroll
                for (int cb = 0; cb < 2; cb++)
                    wmma::load_matrix_sync(bf[cb], cw + (wbt * 32 + cb * 16) * LDW + kk * 16, LDW);
                #pragma unroll
                for (int g = 0; g < 4; g++) {
                    wmma::fragment<wmma::matrix_a, 16, 16, 16, half, wmma::row_major> af;
                    wmma::load_matrix_sync(af, Ws + (g * 32 + wj * 16) * LDH + ch * 64 + kk * 16, LDH);
                    wmma::mma_sync(acc[g][0], af, bf[0], acc[g][0]);
                    wmma::mma_sync(acc[g][1], af, bf[1], acc[g][1]);
                }
            }
            __syncthreads();
            if (c + 2 < 4) {
                wait_pair(fbase, c + 2, (unsigned)st);
                CPCHUNK(hb[c & 1], c + 2);
                CPCHUNK(hb[2 + (c & 1)], 4 + c + 2);
                CPC();
            }
        }

        // -------- epilogue --------
        if (wk == 1) {
            #pragma unroll
            for (int g = 0; g < 4; g++)
                #pragma unroll
                for (int cb = 0; cb < 2; cb++)
                    wmma::store_matrix_sync(GS + (wbt * 32 + cb * 16) * 132 + g * 32 + wj * 16,
                                            acc[g][cb], 132, wmma::mem_col_major);
        }
        __syncthreads();

        // all threads: GS += embproj gather (vectorized)
        const float* __restrict__ EP = g_embp[is_dec];
        for (int i = tid; i < 128 * 32; i += THREADS) {
            int b = i >> 5, j4 = (i & 31) * 4;
            int g = j4 >> 5, hh = j4 & 31;
            const float4 ev = *reinterpret_cast<const float4*>(
                &EP[(long)tok_s[b] * G4 + (long)g * H_ + jt * 32 + hh]);
            float4* gp = reinterpret_cast<float4*>(&GS[b * 132 + j4]);
            float4 gv = *gp;
            gv.x += ev.x; gv.y += ev.y; gv.z += ev.z; gv.w += ev.w;
            *gp = gv;
        }
        __syncthreads();

        // wk=0 warps: combine + cell update (c in registers), stage h
        if (wk == 0) {
            #pragma unroll
            for (int cb = 0; cb < 2; cb++) {
                const int bl = wbt * 32 + cb * 16;
                wmma::fragment<wmma::accumulator, 16, 16, 16, float> xf, hn;
                #pragma unroll
                for (int g = 0; g < 4; g++) {
                    wmma::load_matrix_sync(xf, GS + bl * 132 + g * 32 + wj * 16, 132, wmma::mem_col_major);
                    #pragma unroll
                    for (int e = 0; e < 8; e++) acc[g][cb].x[e] += xf.x[e];
                }
                #pragma unroll
                for (int e = 0; e < 8; e++) {
                    float ig = sigm(acc[0][cb].x[e]);
                    float fg = sigm(acc[1][cb].x[e]);
                    float gg = tanhf(acc[2][cb].x[e]);
                    float og = sigm(acc[3][cb].x[e]);
                    float c2 = fg * cfr[cb].x[e] + ig * gg;
                    cfr[cb].x[e] = c2;
                    hn.x[e] = og * tanhf(c2);
                }
                wmma::store_matrix_sync(hout + bl * 36 + wj * 16, hn, 36, wmma::mem_col_major);
            }
        }
        __syncthreads();

        // all threads: write h (fp16) to global (+ hseq if decoder)
        __half* __restrict__ hg2 = g_hf[par ^ 1];
        for (int i = tid; i < 128 * 32; i += THREADS) {
            int b = i >> 5, hh = i & 31;
            __half v = __float2half(hout[b * 36 + hh]);
            hg2[(long)(b0 + b) * H_ + jt * 32 + hh] = v;
            if (is_dec)
                g_hseq[((long)(b0 + b) * (T_ - 1) + t) * H_ + jt * 32 + hh] = v;
        }
        __syncthreads();

        // publish: this CTA completed step st (h[st+1 input] available)
        if (st + 1 < NSTEP && tid == 0) {
            __threadfence();                    // cumulative: covers all threads' h stores
            strel(my_flag, (unsigned)(st + 1));
        }
    }
}

// ---------------- FC head: logits = h_seq @ fc_w^T + fc_b (fp16 in, fp32 acc) ----------
__global__ __launch_bounds__(256, 1) void fc_kernel()
{
    extern __shared__ __align__(16) char smem[];
    __half* bsm = (__half*)smem;
    __half* ab0 = (__half*)(smem + 128 * LDH * 2);
    __half* ab1 = (__half*)(smem + 128 * LDH * 2 + 128 * LDW * 2);

    const int tid = threadIdx.x;
    const int warp = tid >> 5;
    const int wm = warp >> 2;
    const int wn = warp & 3;
    const long m0 = (long)blockIdx.x * 128;

    for (int i = tid; i < 128 * 64; i += 256) {
        int r = i >> 6, q = i & 63;
        cpa16(bsm + r * LDH + q * 8, g_fcw16 + (long)r * H_ + q * 8);
    }
    for (int i = tid; i < 128 * 8; i += 256) {
        int r = i >> 3, q = i & 7;
        cpa16(ab0 + r * LDW + q * 8, g_hseq + (m0 + r) * H_ + q * 8);
    }
    CPC();
    for (int i = tid; i < 128 * 8; i += 256) {
        int r = i >> 3, q = i & 7;
        cpa16(ab1 + r * LDW + q * 8, g_hseq + (m0 + r) * H_ + 64 + q * 8);
    }
    CPC();
    CPW(1);
    __syncthreads();

    wmma::fragment<wmma::accumulator, 16, 16, 16, float> acc[4][2];
    #pragma unroll
    for (int mm = 0; mm < 4; mm++)
        #pragma unroll
        for (int cb = 0; cb < 2; cb++)
            wmma::load_matrix_sync(acc[mm][cb], g_biasfc + wn * 32 + cb * 16, V_, wmma::mem_row_major);

    #pragma unroll 1
    for (int ch = 0; ch < 8; ch++) {
        const __half* ca = (ch & 1) ? ab1 : ab0;
        #pragma unroll
        for (int kk = 0; kk < 4; kk++) {
            wmma::fragment<wmma::matrix_b, 16, 16, 16, half, wmma::col_major> bf[2];
            #pragma unroll
            for (int cb = 0; cb < 2; cb++)
                wmma::load_matrix_sync(bf[cb], bsm + (wn * 32 + cb * 16) * LDH + ch * 64 + kk * 16, LDH);
            #pragma unroll
            for (int mm = 0; mm < 4; mm++) {
                wmma::fragment<wmma::matrix_a, 16, 16, 16, half, wmma::row_major> af;
                wmma::load_matrix_sync(af, ca + (wm * 64 + mm * 16) * LDW + kk * 16, LDW);
                wmma::mma_sync(acc[mm][0], af, bf[0], acc[mm][0]);
                wmma::mma_sync(acc[mm][1], af, bf[1], acc[mm][1]);
            }
        }
        __syncthreads();
        if (ch + 2 < 8) {
            __half* nb = (ch & 1) ? ab1 : ab0;
            for (int i = tid; i < 128 * 8; i += 256) {
                int r = i >> 3, q = i & 7;
                cpa16(nb + r * LDW + q * 8, g_hseq + (m0 + r) * H_ + (ch + 2) * 64 + q * 8);
            }
            CPC();
        }
        if (ch + 1 < 8) {
            if (ch + 2 < 8) { CPW(1); } else { CPW(0); }
            __syncthreads();
        }
    }

    #pragma unroll
    for (int mm = 0; mm < 4; mm++)
        #pragma unroll
        for (int cb = 0; cb < 2; cb++)
            wmma::store_matrix_sync(g_logits + (m0 + wm * 64 + mm * 16) * V_ + wn * 32 + cb * 16,
                                    acc[mm][cb], V_, wmma::mem_row_major);
}

// ---------------- scatter logits into (B, T, V) with zero row at t=0 ----------------
__global__ void out_kernel(float* __restrict__ out)
{
    const long n4 = (long)B_ * T_ * V_ / 4;
    for (long i = (long)blockIdx.x * blockDim.x + threadIdx.x; i < n4;
         i += (long)gridDim.x * blockDim.x) {
        long e = i * 4;
        int  v  = (int)(e % V_);
        long bt = e / V_;
        int  tt = (int)(bt % T_);
        long b  = bt / T_;
        float4 val;
        if (tt == 0) val = make_float4(0.f, 0.f, 0.f, 0.f);
        else val = *reinterpret_cast<const float4*>(
                       &g_logits[(b * (T_ - 1) + (tt - 1)) * V_ + v]);
        reinterpret_cast<float4*>(out)[i] = val;
    }
}

// ---------------- launch ----------------
extern "C" void kernel_launch(void* const* d_in, const int* in_sizes, int n_in,
                              void* d_out, int out_size)
{
    (void)in_sizes; (void)n_in; (void)out_size;
    const int*   src      = (const int*)  d_in[0];
    const int*   target   = (const int*)  d_in[1];
    const float* emb      = (const float*)d_in[2];
    const float* dec_emb  = (const float*)d_in[3];
    const float* enc_wih  = (const float*)d_in[4];
    const float* enc_whh  = (const float*)d_in[5];
    const float* enc_bih  = (const float*)d_in[6];
    const float* enc_bhh  = (const float*)d_in[7];
    const float* dec_wih  = (const float*)d_in[8];
    const float* dec_whh  = (const float*)d_in[9];
    const float* dec_bih  = (const float*)d_in[10];
    const float* dec_bhh  = (const float*)d_in[11];
    const float* fc_w     = (const float*)d_in[12];
    const float* fc_b     = (const float*)d_in[13];
    float* out = (float*)d_out;

    cudaFuncSetAttribute(seq_kernel, cudaFuncAttributeMaxDynamicSharedMemorySize, SEQ_SMEM);
    cudaFuncSetAttribute(fc_kernel,  cudaFuncAttributeMaxDynamicSharedMemorySize, FC_SMEM);

    prep_embproj<<<dim3(V_, G4 / 256), 256>>>(emb,     enc_wih, enc_bih, enc_bhh, 0);
    prep_embproj<<<dim3(V_, G4 / 256), 256>>>(dec_emb, dec_wih, dec_bih, dec_bhh, 1);
    prep2<<<2048, 256>>>(enc_whh, dec_whh, fc_w, fc_b);

    seq_kernel<<<NCTA, THREADS, SEQ_SMEM>>>(src, target);

    fc_kernel<<<(B_ * (T_ - 1)) / 128, 256, FC_SMEM>>>();
    out_kernel<<<2048, 256>>>(out);
}